// round 9
// baseline (speedup 1.0000x reference)
#include <cuda_runtime.h>

// Problem constants (fixed shapes from reference setup_inputs)
#define TOK   16384          // B*T
#define DD    512            // feature dim
#define KC    4096           // number of centers
#define DOUT  1024           // output dim
#define EPSV  1e-6f

// GEMM tiling
#define BM    128
#define BN    128
#define KB    16
#define NS    (DD / KB)      // 32 k-stages
#define LDP   132            // padded smem row (132*4B = 528B, 16B aligned, conflict-reducing)
#define NTILES (KC / BN)     // 32 center tiles per token

// Scratch (static device globals: allocation-free)
__device__ float g_P[(size_t)KC * DOUT];       // centers @ W + b   (16 MB)
__device__ float g_h[KC];                      // 0.5 * ||c_k||^2
__device__ float g_pVal[(size_t)TOK * NTILES]; // per-tile argmax partials
__device__ int   g_pIdx[(size_t)TOK * NTILES];

typedef unsigned long long u64;

// ---- packed f32x2 helpers (sm_103a dual-rate fp32) ----
__device__ __forceinline__ u64 ffma2(u64 a, u64 b, u64 c) {
    u64 d;
    asm("fma.rn.f32x2 %0, %1, %2, %3;" : "=l"(d) : "l"(a), "l"(b), "l"(c));
    return d;
}
__device__ __forceinline__ u64 splat2(float x) {
    u64 d; unsigned u = __float_as_uint(x);
    asm("mov.b64 %0, {%1, %1};" : "=l"(d) : "r"(u));
    return d;
}
__device__ __forceinline__ float2 unpack2(u64 p) {
    unsigned lo, hi;
    asm("mov.b64 {%0, %1}, %2;" : "=r"(lo), "=r"(hi) : "l"(p));
    return make_float2(__uint_as_float(lo), __uint_as_float(hi));
}

// ============================================================
// K0: g_h[k] = 0.5 * sum_d centers[k,d]^2      (one warp per k)
// ============================================================
__global__ void k_c2(const float* __restrict__ centers) {
    int k    = blockIdx.x * 8 + (threadIdx.x >> 5);
    int lane = threadIdx.x & 31;
    const float4* row = (const float4*)(centers + (size_t)k * DD);
    float s = 0.0f;
    #pragma unroll
    for (int i = lane; i < DD / 4; i += 32) {
        float4 v = row[i];
        s += v.x * v.x + v.y * v.y + v.z * v.z + v.w * v.w;
    }
    #pragma unroll
    for (int off = 16; off; off >>= 1) s += __shfl_xor_sync(0xffffffffu, s, off);
    if (lane == 0) g_h[k] = 0.5f * s;
}

// ============================================================
// K1: g_P = centers @ W + b    (KC x DOUT) = (KC x DD)(DD x DOUT)
//     128x128x16 double-buffered SGEMM, packed FFMA2
// ============================================================
__global__ void k_pgemm(const float* __restrict__ C, const float* __restrict__ W,
                        const float* __restrict__ bias) {
    __shared__ __align__(16) float As[2][KB][LDP];
    __shared__ __align__(16) float Bs[2][KB][LDP];

    const int n0  = blockIdx.x * BN;
    const int m0  = blockIdx.y * BM;
    const int tid = threadIdx.x;
    const int tx  = tid & 15;
    const int ty  = tid >> 4;

    u64 acc[4][8];
    #pragma unroll
    for (int i = 0; i < 4; i++)
        #pragma unroll
        for (int j = 0; j < 8; j++) acc[i][j] = 0ull;

    // stage 0 -> smem[0]
    #pragma unroll
    for (int i = 0; i < 2; i++) {
        int v = tid * 2 + i;
        int mi = v >> 2, k4 = v & 3;                 // A: transpose into [k][m]
        float4 a = *(const float4*)(C + (size_t)(m0 + mi) * DD + k4 * 4);
        As[0][k4 * 4 + 0][mi] = a.x; As[0][k4 * 4 + 1][mi] = a.y;
        As[0][k4 * 4 + 2][mi] = a.z; As[0][k4 * 4 + 3][mi] = a.w;
        int ki = v >> 5, o4 = v & 31;                // B (W): direct copy [k][o]
        float4 b = *(const float4*)(W + (size_t)ki * DOUT + n0 + o4 * 4);
        *(float4*)&Bs[0][ki][o4 * 4] = b;
    }
    __syncthreads();

    for (int s = 0; s < NS; s++) {
        int buf = s & 1;
        float4 ra[2], rb[2];
        if (s + 1 < NS) {
            int d0 = (s + 1) * KB;
            #pragma unroll
            for (int i = 0; i < 2; i++) {
                int v = tid * 2 + i;
                int mi = v >> 2, k4 = v & 3;
                ra[i] = *(const float4*)(C + (size_t)(m0 + mi) * DD + d0 + k4 * 4);
                int ki = v >> 5, o4 = v & 31;
                rb[i] = *(const float4*)(W + (size_t)(d0 + ki) * DOUT + n0 + o4 * 4);
            }
        }
        #pragma unroll
        for (int kk = 0; kk < KB; kk++) {
            const double* ar = (const double*)&As[buf][kk][ty * 8];
            u64 ap0 = __double_as_longlong(ar[0]);
            u64 ap1 = __double_as_longlong(ar[1]);
            u64 ap2 = __double_as_longlong(ar[2]);
            u64 ap3 = __double_as_longlong(ar[3]);
            const float* br = &Bs[buf][kk][tx * 8];
            float4 b0 = *(const float4*)br;
            float4 b1 = *(const float4*)(br + 4);
            u64 bp[8];
            bp[0] = splat2(b0.x); bp[1] = splat2(b0.y); bp[2] = splat2(b0.z); bp[3] = splat2(b0.w);
            bp[4] = splat2(b1.x); bp[5] = splat2(b1.y); bp[6] = splat2(b1.z); bp[7] = splat2(b1.w);
            #pragma unroll
            for (int j = 0; j < 8; j++) {
                acc[0][j] = ffma2(ap0, bp[j], acc[0][j]);
                acc[1][j] = ffma2(ap1, bp[j], acc[1][j]);
                acc[2][j] = ffma2(ap2, bp[j], acc[2][j]);
                acc[3][j] = ffma2(ap3, bp[j], acc[3][j]);
            }
        }
        if (s + 1 < NS) {
            #pragma unroll
            for (int i = 0; i < 2; i++) {
                int v = tid * 2 + i;
                int mi = v >> 2, k4 = v & 3;
                As[buf ^ 1][k4 * 4 + 0][mi] = ra[i].x;
                As[buf ^ 1][k4 * 4 + 1][mi] = ra[i].y;
                As[buf ^ 1][k4 * 4 + 2][mi] = ra[i].z;
                As[buf ^ 1][k4 * 4 + 3][mi] = ra[i].w;
                int ki = v >> 5, o4 = v & 31;
                *(float4*)&Bs[buf ^ 1][ki][o4 * 4] = rb[i];
            }
            __syncthreads();
        }
    }

    // epilogue: add bias, store P
    float bv[8];
    #pragma unroll
    for (int j = 0; j < 8; j++) bv[j] = bias[n0 + tx * 8 + j];
    #pragma unroll
    for (int ip = 0; ip < 4; ip++) {
        float v0[8], v1[8];
        #pragma unroll
        for (int j = 0; j < 8; j++) {
            float2 p = unpack2(acc[ip][j]);
            v0[j] = p.x + bv[j];
            v1[j] = p.y + bv[j];
        }
        int r0 = m0 + ty * 8 + ip * 2;
        float* d0p = g_P + (size_t)r0 * DOUT + n0 + tx * 8;
        float* d1p = d0p + DOUT;
        *(float4*)(d0p)     = make_float4(v0[0], v0[1], v0[2], v0[3]);
        *(float4*)(d0p + 4) = make_float4(v0[4], v0[5], v0[6], v0[7]);
        *(float4*)(d1p)     = make_float4(v1[0], v1[1], v1[2], v1[3]);
        *(float4*)(d1p + 4) = make_float4(v1[4], v1[5], v1[6], v1[7]);
    }
}

// ============================================================
// K2: argmax_k ( <x+eps, c_k> - 0.5*||c_k||^2 )  fused SGEMM
//     grid = (KC/BN, TOK/BM); writes per-tile (val,idx) partials
// ============================================================
__global__ void k_argmax(const float* __restrict__ X, const float* __restrict__ C) {
    __shared__ __align__(16) float As[2][KB][LDP];
    __shared__ __align__(16) float Bs[2][KB][LDP];

    const int ct  = blockIdx.x;           // center tile
    const int n0  = ct * BN;
    const int m0  = blockIdx.y * BM;
    const int tid = threadIdx.x;
    const int tx  = tid & 15;
    const int ty  = tid >> 4;

    u64 acc[4][8];
    #pragma unroll
    for (int i = 0; i < 4; i++)
        #pragma unroll
        for (int j = 0; j < 8; j++) acc[i][j] = 0ull;

    // stage 0 (A carries the +EPS shift; B = centers, transpose-loaded)
    #pragma unroll
    for (int i = 0; i < 2; i++) {
        int v = tid * 2 + i;
        int mi = v >> 2, k4 = v & 3;
        float4 a = *(const float4*)(X + (size_t)(m0 + mi) * DD + k4 * 4);
        As[0][k4 * 4 + 0][mi] = a.x + EPSV; As[0][k4 * 4 + 1][mi] = a.y + EPSV;
        As[0][k4 * 4 + 2][mi] = a.z + EPSV; As[0][k4 * 4 + 3][mi] = a.w + EPSV;
        float4 b = *(const float4*)(C + (size_t)(n0 + mi) * DD + k4 * 4);
        Bs[0][k4 * 4 + 0][mi] = b.x; Bs[0][k4 * 4 + 1][mi] = b.y;
        Bs[0][k4 * 4 + 2][mi] = b.z; Bs[0][k4 * 4 + 3][mi] = b.w;
    }
    __syncthreads();

    for (int s = 0; s < NS; s++) {
        int buf = s & 1;
        float4 ra[2], rb[2];
        if (s + 1 < NS) {
            int d0 = (s + 1) * KB;
            #pragma unroll
            for (int i = 0; i < 2; i++) {
                int v = tid * 2 + i;
                int mi = v >> 2, k4 = v & 3;
                ra[i] = *(const float4*)(X + (size_t)(m0 + mi) * DD + d0 + k4 * 4);
                rb[i] = *(const float4*)(C + (size_t)(n0 + mi) * DD + d0 + k4 * 4);
            }
        }
        #pragma unroll
        for (int kk = 0; kk < KB; kk++) {
            const double* ar = (const double*)&As[buf][kk][ty * 8];
            u64 ap0 = __double_as_longlong(ar[0]);
            u64 ap1 = __double_as_longlong(ar[1]);
            u64 ap2 = __double_as_longlong(ar[2]);
            u64 ap3 = __double_as_longlong(ar[3]);
            const float* br = &Bs[buf][kk][tx * 8];
            float4 b0 = *(const float4*)br;
            float4 b1 = *(const float4*)(br + 4);
            u64 bp[8];
            bp[0] = splat2(b0.x); bp[1] = splat2(b0.y); bp[2] = splat2(b0.z); bp[3] = splat2(b0.w);
            bp[4] = splat2(b1.x); bp[5] = splat2(b1.y); bp[6] = splat2(b1.z); bp[7] = splat2(b1.w);
            #pragma unroll
            for (int j = 0; j < 8; j++) {
                acc[0][j] = ffma2(ap0, bp[j], acc[0][j]);
                acc[1][j] = ffma2(ap1, bp[j], acc[1][j]);
                acc[2][j] = ffma2(ap2, bp[j], acc[2][j]);
                acc[3][j] = ffma2(ap3, bp[j], acc[3][j]);
            }
        }
        if (s + 1 < NS) {
            #pragma unroll
            for (int i = 0; i < 2; i++) {
                int v = tid * 2 + i;
                int mi = v >> 2, k4 = v & 3;
                As[buf ^ 1][k4 * 4 + 0][mi] = ra[i].x + EPSV;
                As[buf ^ 1][k4 * 4 + 1][mi] = ra[i].y + EPSV;
                As[buf ^ 1][k4 * 4 + 2][mi] = ra[i].z + EPSV;
                As[buf ^ 1][k4 * 4 + 3][mi] = ra[i].w + EPSV;
                Bs[buf ^ 1][k4 * 4 + 0][mi] = rb[i].x;
                Bs[buf ^ 1][k4 * 4 + 1][mi] = rb[i].y;
                Bs[buf ^ 1][k4 * 4 + 2][mi] = rb[i].z;
                Bs[buf ^ 1][k4 * 4 + 3][mi] = rb[i].w;
            }
            __syncthreads();
        }
    }

    // fused argmax epilogue (tie -> lowest global center index == jnp.argmin behavior)
    float hh[8];
    #pragma unroll
    for (int j = 0; j < 8; j++) hh[j] = g_h[n0 + tx * 8 + j];

    #pragma unroll
    for (int r = 0; r < 8; r++) {
        float best = -3.0e38f;
        int   bidx = 0x7fffffff;
        #pragma unroll
        for (int j = 0; j < 8; j++) {
            float2 p = unpack2(acc[r >> 1][j]);
            float v = ((r & 1) ? p.y : p.x) - hh[j];
            int gidx = n0 + tx * 8 + j;
            if (v > best) { best = v; bidx = gidx; }   // ascending j -> lowest idx on tie
        }
        // reduce across the 16 tx-lanes owning this row (same ty => same half-warp)
        #pragma unroll
        for (int off = 8; off; off >>= 1) {
            float ov = __shfl_down_sync(0xffffffffu, best, off, 16);
            int   oi = __shfl_down_sync(0xffffffffu, bidx, off, 16);
            if (ov > best || (ov == best && oi < bidx)) { best = ov; bidx = oi; }
        }
        if (tx == 0) {
            int m = m0 + ty * 8 + r;
            g_pVal[(size_t)m * NTILES + ct] = best;
            g_pIdx[(size_t)m * NTILES + ct] = bidx;
        }
    }
}

// ============================================================
// K3: per-token reduce of 32 partials + gather row of g_P
// ============================================================
__global__ void k_gather(float* __restrict__ out) {
    const int m = blockIdx.x;
    __shared__ int s_sel;
    if (threadIdx.x < 32) {
        float v  = g_pVal[(size_t)m * NTILES + threadIdx.x];
        int   id = g_pIdx[(size_t)m * NTILES + threadIdx.x];
        #pragma unroll
        for (int off = 16; off; off >>= 1) {
            float ov = __shfl_down_sync(0xffffffffu, v, off);
            int   oi = __shfl_down_sync(0xffffffffu, id, off);
            if (ov > v || (ov == v && oi < id)) { v = ov; id = oi; }
        }
        if (threadIdx.x == 0) s_sel = id;
    }
    __syncthreads();
    const float4* src = (const float4*)(g_P + (size_t)s_sel * DOUT);
    float4*       dst = (float4*)(out + (size_t)m * DOUT);
    dst[threadIdx.x] = src[threadIdx.x];   // 256 threads * float4 = 1024 floats
}

// ============================================================
extern "C" void kernel_launch(void* const* d_in, const int* in_sizes, int n_in,
                              void* d_out, int out_size) {
    const float* x       = (const float*)d_in[0];   // [4,4096,512]
    const float* centers = (const float*)d_in[1];   // [4096,512]
    const float* W       = (const float*)d_in[2];   // [512,1024]
    const float* bias    = (const float*)d_in[3];   // [1024]
    float* out = (float*)d_out;                     // [4,4096,1024]

    (void)in_sizes; (void)n_in; (void)out_size;

    k_c2    <<<KC / 8, 256>>>(centers);
    k_pgemm <<<dim3(DOUT / BN, KC / BM), 256>>>(centers, W, bias);
    k_argmax<<<dim3(KC / BN, TOK / BM), 256>>>(x, centers);
    k_gather<<<TOK, 256>>>(out);
}

// round 10
// speedup vs baseline: 1.0017x; 1.0017x over previous
#include <cuda_runtime.h>

// Problem constants (fixed shapes from reference setup_inputs)
#define TOK   16384          // B*T
#define DD    512            // feature dim
#define KC    4096           // number of centers
#define DOUT  1024           // output dim
#define EPSV  1e-6f

// GEMM tiling
#define BM    128
#define BN    128
#define KB    16
#define NS    (DD / KB)      // 32 k-stages
#define LDP   132            // padded smem row (132*4B = 528B, 16B aligned, conflict-reducing)
#define NTILES (KC / BN)     // 32 center tiles per token

// Scratch (static device globals: allocation-free)
__device__ float g_P[(size_t)KC * DOUT];       // centers @ W + b   (16 MB)
__device__ float g_h[KC];                      // 0.5 * ||c_k||^2
__device__ float g_pVal[(size_t)TOK * NTILES]; // per-tile argmax partials
__device__ int   g_pIdx[(size_t)TOK * NTILES];

typedef unsigned long long u64;

// ---- packed f32x2 helpers (sm_103a dual-rate fp32) ----
__device__ __forceinline__ u64 ffma2(u64 a, u64 b, u64 c) {
    u64 d;
    asm("fma.rn.f32x2 %0, %1, %2, %3;" : "=l"(d) : "l"(a), "l"(b), "l"(c));
    return d;
}
__device__ __forceinline__ u64 splat2(float x) {
    u64 d; unsigned u = __float_as_uint(x);
    asm("mov.b64 %0, {%1, %1};" : "=l"(d) : "r"(u));
    return d;
}
__device__ __forceinline__ float2 unpack2(u64 p) {
    unsigned lo, hi;
    asm("mov.b64 {%0, %1}, %2;" : "=r"(lo), "=r"(hi) : "l"(p));
    return make_float2(__uint_as_float(lo), __uint_as_float(hi));
}

// ============================================================
// K0: g_h[k] = 0.5 * sum_d centers[k,d]^2      (one warp per k)
// ============================================================
__global__ void k_c2(const float* __restrict__ centers) {
    int k    = blockIdx.x * 8 + (threadIdx.x >> 5);
    int lane = threadIdx.x & 31;
    const float4* row = (const float4*)(centers + (size_t)k * DD);
    float s = 0.0f;
    #pragma unroll
    for (int i = lane; i < DD / 4; i += 32) {
        float4 v = row[i];
        s += v.x * v.x + v.y * v.y + v.z * v.z + v.w * v.w;
    }
    #pragma unroll
    for (int off = 16; off; off >>= 1) s += __shfl_xor_sync(0xffffffffu, s, off);
    if (lane == 0) g_h[k] = 0.5f * s;
}

// ============================================================
// K1: g_P = centers @ W + b    (KC x DOUT) = (KC x DD)(DD x DOUT)
//     128x128x16 double-buffered SGEMM, packed FFMA2
// ============================================================
__global__ void k_pgemm(const float* __restrict__ C, const float* __restrict__ W,
                        const float* __restrict__ bias) {
    __shared__ __align__(16) float As[2][KB][LDP];
    __shared__ __align__(16) float Bs[2][KB][LDP];

    const int n0  = blockIdx.x * BN;
    const int m0  = blockIdx.y * BM;
    const int tid = threadIdx.x;
    const int tx  = tid & 15;
    const int ty  = tid >> 4;

    u64 acc[4][8];
    #pragma unroll
    for (int i = 0; i < 4; i++)
        #pragma unroll
        for (int j = 0; j < 8; j++) acc[i][j] = 0ull;

    // stage 0 -> smem[0]
    #pragma unroll
    for (int i = 0; i < 2; i++) {
        int v = tid * 2 + i;
        int mi = v >> 2, k4 = v & 3;                 // A: transpose into [k][m]
        float4 a = *(const float4*)(C + (size_t)(m0 + mi) * DD + k4 * 4);
        As[0][k4 * 4 + 0][mi] = a.x; As[0][k4 * 4 + 1][mi] = a.y;
        As[0][k4 * 4 + 2][mi] = a.z; As[0][k4 * 4 + 3][mi] = a.w;
        int ki = v >> 5, o4 = v & 31;                // B (W): direct copy [k][o]
        float4 b = *(const float4*)(W + (size_t)ki * DOUT + n0 + o4 * 4);
        *(float4*)&Bs[0][ki][o4 * 4] = b;
    }
    __syncthreads();

    for (int s = 0; s < NS; s++) {
        int buf = s & 1;
        float4 ra[2], rb[2];
        if (s + 1 < NS) {
            int d0 = (s + 1) * KB;
            #pragma unroll
            for (int i = 0; i < 2; i++) {
                int v = tid * 2 + i;
                int mi = v >> 2, k4 = v & 3;
                ra[i] = *(const float4*)(C + (size_t)(m0 + mi) * DD + d0 + k4 * 4);
                int ki = v >> 5, o4 = v & 31;
                rb[i] = *(const float4*)(W + (size_t)(d0 + ki) * DOUT + n0 + o4 * 4);
            }
        }
        #pragma unroll
        for (int kk = 0; kk < KB; kk++) {
            const double* ar = (const double*)&As[buf][kk][ty * 8];
            u64 ap0 = __double_as_longlong(ar[0]);
            u64 ap1 = __double_as_longlong(ar[1]);
            u64 ap2 = __double_as_longlong(ar[2]);
            u64 ap3 = __double_as_longlong(ar[3]);
            const float* br = &Bs[buf][kk][tx * 8];
            float4 b0 = *(const float4*)br;
            float4 b1 = *(const float4*)(br + 4);
            u64 bp[8];
            bp[0] = splat2(b0.x); bp[1] = splat2(b0.y); bp[2] = splat2(b0.z); bp[3] = splat2(b0.w);
            bp[4] = splat2(b1.x); bp[5] = splat2(b1.y); bp[6] = splat2(b1.z); bp[7] = splat2(b1.w);
            #pragma unroll
            for (int j = 0; j < 8; j++) {
                acc[0][j] = ffma2(ap0, bp[j], acc[0][j]);
                acc[1][j] = ffma2(ap1, bp[j], acc[1][j]);
                acc[2][j] = ffma2(ap2, bp[j], acc[2][j]);
                acc[3][j] = ffma2(ap3, bp[j], acc[3][j]);
            }
        }
        if (s + 1 < NS) {
            #pragma unroll
            for (int i = 0; i < 2; i++) {
                int v = tid * 2 + i;
                int mi = v >> 2, k4 = v & 3;
                As[buf ^ 1][k4 * 4 + 0][mi] = ra[i].x;
                As[buf ^ 1][k4 * 4 + 1][mi] = ra[i].y;
                As[buf ^ 1][k4 * 4 + 2][mi] = ra[i].z;
                As[buf ^ 1][k4 * 4 + 3][mi] = ra[i].w;
                int ki = v >> 5, o4 = v & 31;
                *(float4*)&Bs[buf ^ 1][ki][o4 * 4] = rb[i];
            }
            __syncthreads();
        }
    }

    // epilogue: add bias, store P
    float bv[8];
    #pragma unroll
    for (int j = 0; j < 8; j++) bv[j] = bias[n0 + tx * 8 + j];
    #pragma unroll
    for (int ip = 0; ip < 4; ip++) {
        float v0[8], v1[8];
        #pragma unroll
        for (int j = 0; j < 8; j++) {
            float2 p = unpack2(acc[ip][j]);
            v0[j] = p.x + bv[j];
            v1[j] = p.y + bv[j];
        }
        int r0 = m0 + ty * 8 + ip * 2;
        float* d0p = g_P + (size_t)r0 * DOUT + n0 + tx * 8;
        float* d1p = d0p + DOUT;
        *(float4*)(d0p)     = make_float4(v0[0], v0[1], v0[2], v0[3]);
        *(float4*)(d0p + 4) = make_float4(v0[4], v0[5], v0[6], v0[7]);
        *(float4*)(d1p)     = make_float4(v1[0], v1[1], v1[2], v1[3]);
        *(float4*)(d1p + 4) = make_float4(v1[4], v1[5], v1[6], v1[7]);
    }
}

// ============================================================
// K2: argmax_k ( <x+eps, c_k> - 0.5*||c_k||^2 )  fused SGEMM
//     grid = (KC/BN, TOK/BM); writes per-tile (val,idx) partials
// ============================================================
__global__ void k_argmax(const float* __restrict__ X, const float* __restrict__ C) {
    __shared__ __align__(16) float As[2][KB][LDP];
    __shared__ __align__(16) float Bs[2][KB][LDP];

    const int ct  = blockIdx.x;           // center tile
    const int n0  = ct * BN;
    const int m0  = blockIdx.y * BM;
    const int tid = threadIdx.x;
    const int tx  = tid & 15;
    const int ty  = tid >> 4;

    u64 acc[4][8];
    #pragma unroll
    for (int i = 0; i < 4; i++)
        #pragma unroll
        for (int j = 0; j < 8; j++) acc[i][j] = 0ull;

    // stage 0 (A carries the +EPS shift; B = centers, transpose-loaded)
    #pragma unroll
    for (int i = 0; i < 2; i++) {
        int v = tid * 2 + i;
        int mi = v >> 2, k4 = v & 3;
        float4 a = *(const float4*)(X + (size_t)(m0 + mi) * DD + k4 * 4);
        As[0][k4 * 4 + 0][mi] = a.x + EPSV; As[0][k4 * 4 + 1][mi] = a.y + EPSV;
        As[0][k4 * 4 + 2][mi] = a.z + EPSV; As[0][k4 * 4 + 3][mi] = a.w + EPSV;
        float4 b = *(const float4*)(C + (size_t)(n0 + mi) * DD + k4 * 4);
        Bs[0][k4 * 4 + 0][mi] = b.x; Bs[0][k4 * 4 + 1][mi] = b.y;
        Bs[0][k4 * 4 + 2][mi] = b.z; Bs[0][k4 * 4 + 3][mi] = b.w;
    }
    __syncthreads();

    for (int s = 0; s < NS; s++) {
        int buf = s & 1;
        float4 ra[2], rb[2];
        if (s + 1 < NS) {
            int d0 = (s + 1) * KB;
            #pragma unroll
            for (int i = 0; i < 2; i++) {
                int v = tid * 2 + i;
                int mi = v >> 2, k4 = v & 3;
                ra[i] = *(const float4*)(X + (size_t)(m0 + mi) * DD + d0 + k4 * 4);
                rb[i] = *(const float4*)(C + (size_t)(n0 + mi) * DD + d0 + k4 * 4);
            }
        }
        #pragma unroll
        for (int kk = 0; kk < KB; kk++) {
            const double* ar = (const double*)&As[buf][kk][ty * 8];
            u64 ap0 = __double_as_longlong(ar[0]);
            u64 ap1 = __double_as_longlong(ar[1]);
            u64 ap2 = __double_as_longlong(ar[2]);
            u64 ap3 = __double_as_longlong(ar[3]);
            const float* br = &Bs[buf][kk][tx * 8];
            float4 b0 = *(const float4*)br;
            float4 b1 = *(const float4*)(br + 4);
            u64 bp[8];
            bp[0] = splat2(b0.x); bp[1] = splat2(b0.y); bp[2] = splat2(b0.z); bp[3] = splat2(b0.w);
            bp[4] = splat2(b1.x); bp[5] = splat2(b1.y); bp[6] = splat2(b1.z); bp[7] = splat2(b1.w);
            #pragma unroll
            for (int j = 0; j < 8; j++) {
                acc[0][j] = ffma2(ap0, bp[j], acc[0][j]);
                acc[1][j] = ffma2(ap1, bp[j], acc[1][j]);
                acc[2][j] = ffma2(ap2, bp[j], acc[2][j]);
                acc[3][j] = ffma2(ap3, bp[j], acc[3][j]);
            }
        }
        if (s + 1 < NS) {
            #pragma unroll
            for (int i = 0; i < 2; i++) {
                int v = tid * 2 + i;
                int mi = v >> 2, k4 = v & 3;
                As[buf ^ 1][k4 * 4 + 0][mi] = ra[i].x + EPSV;
                As[buf ^ 1][k4 * 4 + 1][mi] = ra[i].y + EPSV;
                As[buf ^ 1][k4 * 4 + 2][mi] = ra[i].z + EPSV;
                As[buf ^ 1][k4 * 4 + 3][mi] = ra[i].w + EPSV;
                Bs[buf ^ 1][k4 * 4 + 0][mi] = rb[i].x;
                Bs[buf ^ 1][k4 * 4 + 1][mi] = rb[i].y;
                Bs[buf ^ 1][k4 * 4 + 2][mi] = rb[i].z;
                Bs[buf ^ 1][k4 * 4 + 3][mi] = rb[i].w;
            }
            __syncthreads();
        }
    }

    // fused argmax epilogue (tie -> lowest global center index == jnp.argmin behavior)
    float hh[8];
    #pragma unroll
    for (int j = 0; j < 8; j++) hh[j] = g_h[n0 + tx * 8 + j];

    #pragma unroll
    for (int r = 0; r < 8; r++) {
        float best = -3.0e38f;
        int   bidx = 0x7fffffff;
        #pragma unroll
        for (int j = 0; j < 8; j++) {
            float2 p = unpack2(acc[r >> 1][j]);
            float v = ((r & 1) ? p.y : p.x) - hh[j];
            int gidx = n0 + tx * 8 + j;
            if (v > best) { best = v; bidx = gidx; }   // ascending j -> lowest idx on tie
        }
        // reduce across the 16 tx-lanes owning this row (same ty => same half-warp)
        #pragma unroll
        for (int off = 8; off; off >>= 1) {
            float ov = __shfl_down_sync(0xffffffffu, best, off, 16);
            int   oi = __shfl_down_sync(0xffffffffu, bidx, off, 16);
            if (ov > best || (ov == best && oi < bidx)) { best = ov; bidx = oi; }
        }
        if (tx == 0) {
            int m = m0 + ty * 8 + r;
            g_pVal[(size_t)m * NTILES + ct] = best;
            g_pIdx[(size_t)m * NTILES + ct] = bidx;
        }
    }
}

// ============================================================
// K3: per-token reduce of 32 partials + gather row of g_P
// ============================================================
__global__ void k_gather(float* __restrict__ out) {
    const int m = blockIdx.x;
    __shared__ int s_sel;
    if (threadIdx.x < 32) {
        float v  = g_pVal[(size_t)m * NTILES + threadIdx.x];
        int   id = g_pIdx[(size_t)m * NTILES + threadIdx.x];
        #pragma unroll
        for (int off = 16; off; off >>= 1) {
            float ov = __shfl_down_sync(0xffffffffu, v, off);
            int   oi = __shfl_down_sync(0xffffffffu, id, off);
            if (ov > v || (ov == v && oi < id)) { v = ov; id = oi; }
        }
        if (threadIdx.x == 0) s_sel = id;
    }
    __syncthreads();
    const float4* src = (const float4*)(g_P + (size_t)s_sel * DOUT);
    float4*       dst = (float4*)(out + (size_t)m * DOUT);
    dst[threadIdx.x] = src[threadIdx.x];   // 256 threads * float4 = 1024 floats
}

// ============================================================
extern "C" void kernel_launch(void* const* d_in, const int* in_sizes, int n_in,
                              void* d_out, int out_size) {
    const float* x       = (const float*)d_in[0];   // [4,4096,512]
    const float* centers = (const float*)d_in[1];   // [4096,512]
    const float* W       = (const float*)d_in[2];   // [512,1024]
    const float* bias    = (const float*)d_in[3];   // [1024]
    float* out = (float*)d_out;                     // [4,4096,1024]

    (void)in_sizes; (void)n_in; (void)out_size;

    k_c2    <<<KC / 8, 256>>>(centers);
    k_pgemm <<<dim3(DOUT / BN, KC / BM), 256>>>(centers, W, bias);
    k_argmax<<<dim3(KC / BN, TOK / BM), 256>>>(x, centers);
    k_gather<<<TOK, 256>>>(out);
}